// round 8
// baseline (speedup 1.0000x reference)
#include <cuda_runtime.h>
#include <cstdint>
#include <math.h>

#define D_DIM 1024
#define B_DIM 2
#define S_DIM 1024
#define NROWS (B_DIM * S_DIM)   // 2048
#define L_DIM 2
#define V_DIM 32000

// GEMM smem geometry (floats), 2-stage pipeline, 128x128 tiles
#define A_STRIDE 36
#define B_STRIDE 136
#define A_TILE (128 * A_STRIDE)          // 4608 floats per stage
#define B_TILE (32 * B_STRIDE)           // 4352 floats per stage
#define GEMM_SMEM_BYTES (2 * (A_TILE + B_TILE) * 4)   // 71680

// ---------------- scratch (device globals; no allocation allowed) ----------------
__device__ float g_x[NROWS * D_DIM];
__device__ float g_q[NROWS * D_DIM];
__device__ float g_k[NROWS * D_DIM];
__device__ float g_v[NROWS * D_DIM];
__device__ float g_o[NROWS * D_DIM];
__device__ float g_beta[NROWS];
__device__ float g_qk[NROWS];

// ---------------- helpers ----------------
__device__ __forceinline__ uint32_t f2tf32(float f) {
    uint32_t u;
    asm("cvt.rna.tf32.f32 %0, %1;" : "=r"(u) : "f"(f));
    return u;
}

__device__ __forceinline__ float2 ffma2(float2 a, float2 b, float2 c) {
    float2 d;
    asm("fma.rn.f32x2 %0, %1, %2, %3;"
        : "=l"(reinterpret_cast<unsigned long long &>(d))
        : "l"(reinterpret_cast<unsigned long long &>(a)),
          "l"(reinterpret_cast<unsigned long long &>(b)),
          "l"(reinterpret_cast<unsigned long long &>(c)));
    return d;
}

__device__ __forceinline__ void mma_tf32(float* c, const uint32_t* a, const uint32_t* b) {
    asm volatile(
        "mma.sync.aligned.m16n8k8.row.col.f32.tf32.tf32.f32 "
        "{%0,%1,%2,%3}, {%4,%5,%6,%7}, {%8,%9}, {%0,%1,%2,%3};"
        : "+f"(c[0]), "+f"(c[1]), "+f"(c[2]), "+f"(c[3])
        : "r"(a[0]), "r"(a[1]), "r"(a[2]), "r"(a[3]), "r"(b[0]), "r"(b[1]));
}

__device__ __forceinline__ void cp16(float* dst, const float* src) {
    uint32_t d = (uint32_t)__cvta_generic_to_shared(dst);
    asm volatile("cp.async.cg.shared.global [%0], [%1], 16;" :: "r"(d), "l"(src));
}
__device__ __forceinline__ void cp_commit() {
    asm volatile("cp.async.commit_group;");
}

__device__ __forceinline__ float silu1(float x) { return x / (1.f + expf(-x)); }

__device__ __forceinline__ float blockReduceSum(float v, float* sh) {
    #pragma unroll
    for (int o = 16; o; o >>= 1) v += __shfl_xor_sync(0xffffffffu, v, o);
    int w = threadIdx.x >> 5;
    if ((threadIdx.x & 31) == 0) sh[w] = v;
    __syncthreads();
    if (threadIdx.x == 0) {
        float s = sh[0];
        #pragma unroll
        for (int i = 1; i < 8; i++) s += sh[i];
        sh[0] = s;
    }
    __syncthreads();
    return sh[0];
}

// ---------------- embedding gather ----------------
__global__ void embed_k(const int* __restrict__ tokens, const float* __restrict__ emb,
                        float* __restrict__ x) {
    int row = blockIdx.x;
    int tok = tokens[row];
    ((float4*)(x + (size_t)row * D_DIM))[threadIdx.x] =
        ((const float4*)(emb + (size_t)tok * D_DIM))[threadIdx.x];
}

// ---------------- GEMM core 128x128 (2-stage) ----------------
// 8 warps (2x4), warp tile 64x32 = 4x4 m16n8k8 mmas.
// SPLIT: 3xTF32 split hi/lo (~fp32 accuracy). SILU: apply silu to output.
template <bool SPLIT, bool SILU>
__device__ __forceinline__ void gemm_body(
    const float* __restrict__ A, const float* __restrict__ B, float* __restrict__ C,
    int N, int K, int bm, int bn, float* sm) {

    int tid  = threadIdx.x;
    int warp = tid >> 5, lane = tid & 31;
    int wm = warp >> 2, wn = warp & 3;
    int g = lane >> 2, tg = lane & 3;

    float acc[4][4][4];
    #pragma unroll
    for (int mt = 0; mt < 4; mt++)
        #pragma unroll
        for (int nt = 0; nt < 4; nt++)
            #pragma unroll
            for (int r = 0; r < 4; r++) acc[mt][nt][r] = 0.f;

    const float* Ab = A + (size_t)(bm * 128) * K;
    const float* Bb = B + bn * 128;

    int arow = tid >> 3;            // 0..31
    int acol = (tid & 7) * 4;
    int brow = tid >> 5;            // 0..7
    int bcol = (tid & 31) * 4;

    const int NT = K >> 5;

    {   // prologue: prefetch tile 0
        float* A0 = sm;
        float* B0 = sm + 2 * A_TILE;
        #pragma unroll
        for (int p = 0; p < 4; p++) {
            int r = arow + p * 32;
            cp16(&A0[r * A_STRIDE + acol], Ab + (size_t)r * K + acol);
        }
        #pragma unroll
        for (int p = 0; p < 4; p++) {
            int r = brow + p * 8;
            cp16(&B0[r * B_STRIDE + bcol], Bb + (size_t)r * N + bcol);
        }
        cp_commit();
    }

    for (int t = 0; t < NT; t++) {
        float* Ac = sm + (t & 1) * A_TILE;
        float* Bc = sm + 2 * A_TILE + (t & 1) * B_TILE;
        if (t + 1 < NT) {
            float* An = sm + ((t + 1) & 1) * A_TILE;
            float* Bn = sm + 2 * A_TILE + ((t + 1) & 1) * B_TILE;
            int k0 = (t + 1) * 32;
            #pragma unroll
            for (int p = 0; p < 4; p++) {
                int r = arow + p * 32;
                cp16(&An[r * A_STRIDE + acol], Ab + (size_t)r * K + k0 + acol);
            }
            #pragma unroll
            for (int p = 0; p < 4; p++) {
                int r = brow + p * 8;
                cp16(&Bn[r * B_STRIDE + bcol], Bb + (size_t)(k0 + r) * N + bcol);
            }
            cp_commit();
            asm volatile("cp.async.wait_group 1;");
        } else {
            asm volatile("cp.async.wait_group 0;");
        }
        __syncthreads();

        #pragma unroll
        for (int kk = 0; kk < 4; kk++) {
            if (!SPLIT) {
                uint32_t bf[4][2];
                #pragma unroll
                for (int nt = 0; nt < 4; nt++) {
                    int cbase = (kk * 8 + tg) * B_STRIDE + wn * 32 + nt * 8 + g;
                    bf[nt][0] = f2tf32(Bc[cbase]);
                    bf[nt][1] = f2tf32(Bc[cbase + 4 * B_STRIDE]);
                }
                #pragma unroll
                for (int mt = 0; mt < 4; mt++) {
                    int rbase = (wm * 64 + mt * 16) * A_STRIDE + kk * 8 + tg;
                    uint32_t af[4];
                    af[0] = f2tf32(Ac[rbase + g * A_STRIDE]);
                    af[1] = f2tf32(Ac[rbase + (g + 8) * A_STRIDE]);
                    af[2] = f2tf32(Ac[rbase + g * A_STRIDE + 4]);
                    af[3] = f2tf32(Ac[rbase + (g + 8) * A_STRIDE + 4]);
                    #pragma unroll
                    for (int nt = 0; nt < 4; nt++)
                        mma_tf32(acc[mt][nt], af, bf[nt]);
                }
            } else {
                uint32_t bfh[4][2], bfl[4][2];
                #pragma unroll
                for (int nt = 0; nt < 4; nt++) {
                    int cbase = (kk * 8 + tg) * B_STRIDE + wn * 32 + nt * 8 + g;
                    float f0 = Bc[cbase];
                    float f1 = Bc[cbase + 4 * B_STRIDE];
                    uint32_t h0 = f2tf32(f0), h1 = f2tf32(f1);
                    bfh[nt][0] = h0; bfh[nt][1] = h1;
                    bfl[nt][0] = f2tf32(f0 - __uint_as_float(h0));
                    bfl[nt][1] = f2tf32(f1 - __uint_as_float(h1));
                }
                #pragma unroll
                for (int mt = 0; mt < 4; mt++) {
                    int rbase = (wm * 64 + mt * 16) * A_STRIDE + kk * 8 + tg;
                    float f0 = Ac[rbase + g * A_STRIDE];
                    float f1 = Ac[rbase + (g + 8) * A_STRIDE];
                    float f2 = Ac[rbase + g * A_STRIDE + 4];
                    float f3 = Ac[rbase + (g + 8) * A_STRIDE + 4];
                    uint32_t afh[4], afl[4];
                    afh[0] = f2tf32(f0); afl[0] = f2tf32(f0 - __uint_as_float(afh[0]));
                    afh[1] = f2tf32(f1); afl[1] = f2tf32(f1 - __uint_as_float(afh[1]));
                    afh[2] = f2tf32(f2); afl[2] = f2tf32(f2 - __uint_as_float(afh[2]));
                    afh[3] = f2tf32(f3); afl[3] = f2tf32(f3 - __uint_as_float(afh[3]));
                    #pragma unroll
                    for (int nt = 0; nt < 4; nt++) {
                        mma_tf32(acc[mt][nt], afh, bfl[nt]);
                        mma_tf32(acc[mt][nt], afl, bfh[nt]);
                        mma_tf32(acc[mt][nt], afh, bfh[nt]);
                    }
                }
            }
        }
        __syncthreads();
    }

    int row0 = bm * 128 + wm * 64;
    int col0 = bn * 128 + wn * 32;
    #pragma unroll
    for (int mt = 0; mt < 4; mt++)
        #pragma unroll
        for (int nt = 0; nt < 4; nt++) {
            int row = row0 + mt * 16 + g;
            int col = col0 + nt * 8 + tg * 2;
            float v0 = acc[mt][nt][0], v1 = acc[mt][nt][1];
            float v2 = acc[mt][nt][2], v3 = acc[mt][nt][3];
            if (SILU) { v0 = silu1(v0); v1 = silu1(v1); v2 = silu1(v2); v3 = silu1(v3); }
            *(float2*)(C + (size_t)row * N + col) = make_float2(v0, v1);
            *(float2*)(C + (size_t)(row + 8) * N + col) = make_float2(v2, v3);
        }
}

// standalone GEMM
template <bool SPLIT>
__global__ __launch_bounds__(256, 2) void gemm_tf32(
    const float* __restrict__ A, const float* __restrict__ B, float* __restrict__ C,
    int M, int N, int K) {
    extern __shared__ float sm[];
    gemm_body<SPLIT, false>(A, B, C, N, K, blockIdx.y, blockIdx.x, sm);
}

// fused QKV: grid z selects weight/output; z==2 (V) applies silu in epilogue
__global__ __launch_bounds__(256, 2) void gemm_qkv(
    const float* __restrict__ X,
    const float* __restrict__ Wq, const float* __restrict__ Wk, const float* __restrict__ Wv,
    float* __restrict__ Q, float* __restrict__ Ko, float* __restrict__ Vo) {
    extern __shared__ float sm[];
    int z = blockIdx.z;
    const float* B = (z == 0) ? Wq : (z == 1) ? Wk : Wv;
    float* C = (z == 0) ? Q : (z == 1) ? Ko : Vo;
    if (z == 2)
        gemm_body<true, true>(X, B, C, D_DIM, D_DIM, blockIdx.y, blockIdx.x, sm);
    else
        gemm_body<true, false>(X, B, C, D_DIM, D_DIM, blockIdx.y, blockIdx.x, sm);
}

// ---------------- beta = sigmoid(x . wb), one warp per row ----------------
__global__ void rowdot_sigmoid(const float* __restrict__ x, const float* __restrict__ w,
                               float* __restrict__ out) {
    int row  = blockIdx.x * 8 + (threadIdx.x >> 5);
    int lane = threadIdx.x & 31;
    const float4* xr = (const float4*)(x + (size_t)row * D_DIM);
    const float4* wr = (const float4*)w;
    float s = 0.f;
    #pragma unroll
    for (int i = lane; i < D_DIM / 4; i += 32) {
        float4 a = xr[i], b = wr[i];
        s += a.x * b.x + a.y * b.y + a.z * b.z + a.w * b.w;
    }
    #pragma unroll
    for (int o = 16; o; o >>= 1) s += __shfl_xor_sync(0xffffffffu, s, o);
    if (lane == 0) out[row] = 1.f / (1.f + expf(-s));
}

// ---------------- y = l2norm(silu(x)) in place, one block per row ----------------
__global__ void silu_l2norm_k(float* __restrict__ x) {
    __shared__ float sh[8];
    float4* xr = (float4*)(x + (size_t)blockIdx.x * D_DIM);
    float4 a = xr[threadIdx.x];
    a.x = silu1(a.x); a.y = silu1(a.y); a.z = silu1(a.z); a.w = silu1(a.w);
    float ss = a.x * a.x + a.y * a.y + a.z * a.z + a.w * a.w;
    float tot = blockReduceSum(ss, sh);
    float r = rsqrtf(tot + 1e-6f);
    a.x *= r; a.y *= r; a.z *= r; a.w *= r;
    xr[threadIdx.x] = a;
}

// ---------------- k := l2norm(silu(k)); qk[row] = k . q (q already normalized) ----------------
__global__ void silu_l2norm_dot_k(float* __restrict__ k, const float* __restrict__ q,
                                  float* __restrict__ qk) {
    __shared__ float sh1[8];
    __shared__ float sh2[8];
    int row = blockIdx.x;
    float4* kr = (float4*)(k + (size_t)row * D_DIM);
    const float4* qr = (const float4*)(q + (size_t)row * D_DIM);
    float4 a = kr[threadIdx.x];
    a.x = silu1(a.x); a.y = silu1(a.y); a.z = silu1(a.z); a.w = silu1(a.w);
    float ss = a.x * a.x + a.y * a.y + a.z * a.z + a.w * a.w;
    float tot = blockReduceSum(ss, sh1);
    float r = rsqrtf(tot + 1e-6f);
    a.x *= r; a.y *= r; a.z *= r; a.w *= r;
    kr[threadIdx.x] = a;
    float4 qv = qr[threadIdx.x];
    float d = a.x * qv.x + a.y * qv.y + a.z * qv.z + a.w * qv.w;
    float dtot = blockReduceSum(d, sh2);
    if (threadIdx.x == 0) qk[row] = dtot;
}

// ---------------- rmsnorm in place, one block per row ----------------
__global__ void rmsnorm_k(float* __restrict__ x, const float* __restrict__ w) {
    __shared__ float sh[8];
    float4* xr = (float4*)(x + (size_t)blockIdx.x * D_DIM);
    float4 a = xr[threadIdx.x];
    float ss = a.x * a.x + a.y * a.y + a.z * a.z + a.w * a.w;
    float tot = blockReduceSum(ss, sh);
    float r = rsqrtf(tot * (1.f / D_DIM) + 1e-5f);
    float4 wv = ((const float4*)w)[threadIdx.x];
    a.x *= r * wv.x; a.y *= r * wv.y; a.z *= r * wv.z; a.w *= r * wv.w;
    xr[threadIdx.x] = a;
}

// ---------------- layernorm in place, one block per row ----------------
__global__ void layernorm_k(float* __restrict__ x, const float* __restrict__ gg,
                            const float* __restrict__ bb) {
    __shared__ float sh1[8];
    __shared__ float sh2[8];
    float4* xr = (float4*)(x + (size_t)blockIdx.x * D_DIM);
    float4 a = xr[threadIdx.x];
    float s  = a.x + a.y + a.z + a.w;
    float ss = a.x * a.x + a.y * a.y + a.z * a.z + a.w * a.w;
    float S  = blockReduceSum(s, sh1);
    float SS = blockReduceSum(ss, sh2);
    float mu  = S * (1.f / D_DIM);
    float var = SS * (1.f / D_DIM) - mu * mu;
    float r = rsqrtf(var + 1e-5f);
    float4 gv = ((const float4*)gg)[threadIdx.x];
    float4 bv = ((const float4*)bb)[threadIdx.x];
    a.x = (a.x - mu) * r * gv.x + bv.x;
    a.y = (a.y - mu) * r * gv.y + bv.y;
    a.z = (a.z - mu) * r * gv.z + bv.z;
    a.w = (a.w - mu) * r * gv.w + bv.w;
    xr[threadIdx.x] = a;
}

// ---------------- delta-rule scan: 2 barriers/step, ping-pong buffers ----------------
// 256 blocks x 256 threads. Block: batch b = blk>>7, 8 columns.
// cg = tid>>7 owns 4 columns; rg = tid&127 owns rows [rg*8, rg*8+8).
// Phase 1 (compute partials, write part[p]) | sync | Phase 2 (reduce part[p]->tot[p],
// stage k/q for t+1 into alternate smem buffer, prefetch v/beta/qk) | sync |
// Phase 3 (consume tot[p], update S, write o) -> loop.
__global__ __launch_bounds__(256) void delta_scan(
    const float* __restrict__ q, const float* __restrict__ k,
    const float* __restrict__ v, const float* __restrict__ beta,
    const float* __restrict__ qk, float* __restrict__ o) {
    __shared__ float sk[2][1024];
    __shared__ float sq[2][1024];
    __shared__ float part[2][16 * 132];
    __shared__ float tot[2][16];

    int tid = threadIdx.x;
    int b = blockIdx.x >> 7;
    int ebase = (blockIdx.x & 127) * 8;
    int cg = tid >> 7;
    int rg = tid & 127;
    int d0 = rg * 8;
    int e0 = ebase + cg * 4;

    float2 S[4][4];
    #pragma unroll
    for (int r = 0; r < 4; r++)
        #pragma unroll
        for (int c = 0; c < 4; c++) S[r][c] = make_float2(0.f, 0.f);

    const float* qb = q + (size_t)b * S_DIM * D_DIM;
    const float* kb = k + (size_t)b * S_DIM * D_DIM;
    const float* vb = v + (size_t)b * S_DIM * D_DIM;
    const float* betab = beta + b * S_DIM;
    const float* qkb   = qk + b * S_DIM;
    float* ob = o + (size_t)b * S_DIM * D_DIM;

    int gj = tid >> 4, sl = tid & 15;   // reduce-stage mapping

    // prologue: stage t=0
    ((float4*)sk[0])[tid] = ((const float4*)kb)[tid];
    ((float4*)sq[0])[tid] = ((const float4*)qb)[tid];
    float4 pv = *(const float4*)(vb + e0);
    float pbeta = betab[0];
    float pqk = qkb[0];
    __syncthreads();

    for (int t = 0; t < S_DIM; t++) {
        int p = t & 1;

        // phase 1: partials with current state
        float4 kA = *(float4*)(sk[p] + d0);
        float4 kB = *(float4*)(sk[p] + d0 + 4);
        float4 qA = *(float4*)(sq[p] + d0);
        float4 qB = *(float4*)(sq[p] + d0 + 4);
        float2 kv[4] = {{kA.x, kA.y}, {kA.z, kA.w}, {kB.x, kB.y}, {kB.z, kB.w}};
        float2 qv[4] = {{qA.x, qA.y}, {qA.z, qA.w}, {qB.x, qB.y}, {qB.z, qB.w}};

        float2 ks2[4], qs2[4];
        #pragma unroll
        for (int c = 0; c < 4; c++) { ks2[c] = make_float2(0.f, 0.f); qs2[c] = make_float2(0.f, 0.f); }
        #pragma unroll
        for (int c = 0; c < 4; c++)
            #pragma unroll
            for (int r = 0; r < 4; r++) {
                ks2[c] = ffma2(kv[r], S[r][c], ks2[c]);
                qs2[c] = ffma2(qv[r], S[r][c], qs2[c]);
            }
        #pragma unroll
        for (int c = 0; c < 4; c++) {
            part[p][(cg * 8 + c) * 132 + rg]     = ks2[c].x + ks2[c].y;
            part[p][(cg * 8 + 4 + c) * 132 + rg] = qs2[c].x + qs2[c].y;
        }
        __syncthreads();   // part[p] visible

        // phase 2: reduce + stage next token
        {
            const float* pg = part[p] + gj * 132;
            float ps = 0.f;
            #pragma unroll
            for (int i = 0; i < 8; i++) ps += pg[sl + 16 * i];
            #pragma unroll
            for (int off = 8; off; off >>= 1) ps += __shfl_down_sync(0xffffffffu, ps, off, 16);
            if (sl == 0) tot[p][gj] = ps;
        }
        float4 nv;
        float nbeta = 0.f, nqk = 0.f;
        if (t + 1 < S_DIM) {
            size_t off = (size_t)(t + 1) * D_DIM;
            ((float4*)sk[p ^ 1])[tid] = ((const float4*)(kb + off))[tid];
            ((float4*)sq[p ^ 1])[tid] = ((const float4*)(qb + off))[tid];
            nv = *(const float4*)(vb + off + e0);
            nbeta = betab[t + 1];
            nqk = qkb[t + 1];
        }
        __syncthreads();   // tot[p] + next k/q visible

        // phase 3: consume
        float vvals[4] = {pv.x, pv.y, pv.z, pv.w};
        float cc[4];
        #pragma unroll
        for (int c = 0; c < 4; c++) {
            float ksv = tot[p][cg * 8 + c];
            cc[c] = pbeta * (vvals[c] - ksv);
            if (rg == 0) ob[(size_t)t * D_DIM + e0 + c] = tot[p][cg * 8 + 4 + c] + pqk * cc[c];
        }
        #pragma unroll
        for (int c = 0; c < 4; c++) {
            float2 c2 = make_float2(cc[c], cc[c]);
            #pragma unroll
            for (int r = 0; r < 4; r++) S[r][c] = ffma2(kv[r], c2, S[r][c]);
        }
        if (t + 1 < S_DIM) { pv = nv; pbeta = nbeta; pqk = nqk; }
    }
}

// ---------------- host orchestration ----------------
extern "C" void kernel_launch(void* const* d_in, const int* in_sizes, int n_in,
                              void* d_out, int out_size) {
    const int*   tokens = (const int*)d_in[0];
    const float* emb    = (const float*)d_in[1];
    const float* Wq     = (const float*)d_in[2];
    const float* Wk     = (const float*)d_in[3];
    const float* Wv     = (const float*)d_in[4];
    const float* Wb     = (const float*)d_in[5];
    const float* Wo     = (const float*)d_in[6];
    const float* rms_w  = (const float*)d_in[7];
    const float* ln_g   = (const float*)d_in[8];
    const float* ln_b   = (const float*)d_in[9];
    const float* head_w = (const float*)d_in[10];
    float* out = (float*)d_out;

    float *x, *qb, *kb, *vb, *ob, *betab, *qkb;
    cudaGetSymbolAddress((void**)&x, g_x);
    cudaGetSymbolAddress((void**)&qb, g_q);
    cudaGetSymbolAddress((void**)&kb, g_k);
    cudaGetSymbolAddress((void**)&vb, g_v);
    cudaGetSymbolAddress((void**)&ob, g_o);
    cudaGetSymbolAddress((void**)&betab, g_beta);
    cudaGetSymbolAddress((void**)&qkb, g_qk);

    cudaFuncSetAttribute(gemm_tf32<true>,  cudaFuncAttributeMaxDynamicSharedMemorySize, GEMM_SMEM_BYTES);
    cudaFuncSetAttribute(gemm_tf32<false>, cudaFuncAttributeMaxDynamicSharedMemorySize, GEMM_SMEM_BYTES);
    cudaFuncSetAttribute(gemm_qkv,         cudaFuncAttributeMaxDynamicSharedMemorySize, GEMM_SMEM_BYTES);

    embed_k<<<NROWS, 256>>>(tokens, emb, x);

    dim3 g1(D_DIM / 128, NROWS / 128);          // (8,16)
    dim3 gqkv(D_DIM / 128, NROWS / 128, 3);     // (8,16,3)
    for (int l = 0; l < L_DIM; l++) {
        const float* wq = Wq + (size_t)l * D_DIM * D_DIM;
        const float* wk = Wk + (size_t)l * D_DIM * D_DIM;
        const float* wv = Wv + (size_t)l * D_DIM * D_DIM;
        const float* wb = Wb + (size_t)l * D_DIM;
        const float* wo = Wo + (size_t)l * D_DIM * D_DIM;
        const float* rw = rms_w + (size_t)l * D_DIM;

        gemm_qkv<<<gqkv, 256, GEMM_SMEM_BYTES>>>(x, wq, wk, wv, qb, kb, vb);
        rowdot_sigmoid<<<NROWS / 8, 256>>>(x, wb, betab);
        silu_l2norm_k<<<NROWS, 256>>>(qb);
        silu_l2norm_dot_k<<<NROWS, 256>>>(kb, qb, qkb);
        delta_scan<<<256, 256>>>(qb, kb, vb, betab, qkb, ob);   // launch index 5 on layer 0
        rmsnorm_k<<<NROWS, 256>>>(ob, rw);
        gemm_tf32<true><<<g1, 256, GEMM_SMEM_BYTES>>>(ob, wo, x, NROWS, D_DIM, D_DIM);
    }
    layernorm_k<<<NROWS, 256>>>(x, ln_g, ln_b);

    dim3 g2(V_DIM / 128, NROWS / 128);   // (250,16)
    gemm_tf32<false><<<g2, 256, GEMM_SMEM_BYTES>>>(x, head_w, out, NROWS, V_DIM, D_DIM);
}

// round 9
// speedup vs baseline: 1.0886x; 1.0886x over previous
#include <cuda_runtime.h>
#include <cstdint>
#include <math.h>

#define D_DIM 1024
#define B_DIM 2
#define S_DIM 1024
#define NROWS (B_DIM * S_DIM)   // 2048
#define L_DIM 2
#define V_DIM 32000

// GEMM smem geometry (floats), 2-stage pipeline, 128x128 tiles
#define A_STRIDE 36
#define B_STRIDE 136
#define A_TILE (128 * A_STRIDE)          // 4608 floats per stage
#define B_TILE (32 * B_STRIDE)           // 4352 floats per stage
#define GEMM_SMEM_BYTES (2 * (A_TILE + B_TILE) * 4)   // 71680

// ---------------- scratch (device globals; no allocation allowed) ----------------
__device__ float g_x[NROWS * D_DIM];
__device__ float g_q[NROWS * D_DIM];
__device__ float g_k[NROWS * D_DIM];
__device__ float g_v[NROWS * D_DIM];
__device__ float g_o[NROWS * D_DIM];
__device__ float g_beta[NROWS];
__device__ float g_qk[NROWS];

// ---------------- helpers ----------------
__device__ __forceinline__ uint32_t f2tf32(float f) {
    uint32_t u;
    asm("cvt.rna.tf32.f32 %0, %1;" : "=r"(u) : "f"(f));
    return u;
}

__device__ __forceinline__ float2 ffma2(float2 a, float2 b, float2 c) {
    float2 d;
    asm("fma.rn.f32x2 %0, %1, %2, %3;"
        : "=l"(reinterpret_cast<unsigned long long &>(d))
        : "l"(reinterpret_cast<unsigned long long &>(a)),
          "l"(reinterpret_cast<unsigned long long &>(b)),
          "l"(reinterpret_cast<unsigned long long &>(c)));
    return d;
}

__device__ __forceinline__ void mma_tf32(float* c, const uint32_t* a, const uint32_t* b) {
    asm volatile(
        "mma.sync.aligned.m16n8k8.row.col.f32.tf32.tf32.f32 "
        "{%0,%1,%2,%3}, {%4,%5,%6,%7}, {%8,%9}, {%0,%1,%2,%3};"
        : "+f"(c[0]), "+f"(c[1]), "+f"(c[2]), "+f"(c[3])
        : "r"(a[0]), "r"(a[1]), "r"(a[2]), "r"(a[3]), "r"(b[0]), "r"(b[1]));
}

__device__ __forceinline__ void cp16(float* dst, const float* src) {
    uint32_t d = (uint32_t)__cvta_generic_to_shared(dst);
    asm volatile("cp.async.cg.shared.global [%0], [%1], 16;" :: "r"(d), "l"(src));
}
__device__ __forceinline__ void cp_commit() {
    asm volatile("cp.async.commit_group;");
}

__device__ __forceinline__ float silu1(float x) { return x / (1.f + expf(-x)); }

__device__ __forceinline__ float blockReduceSum(float v, float* sh) {
    #pragma unroll
    for (int o = 16; o; o >>= 1) v += __shfl_xor_sync(0xffffffffu, v, o);
    int w = threadIdx.x >> 5;
    if ((threadIdx.x & 31) == 0) sh[w] = v;
    __syncthreads();
    if (threadIdx.x == 0) {
        float s = sh[0];
        #pragma unroll
        for (int i = 1; i < 8; i++) s += sh[i];
        sh[0] = s;
    }
    __syncthreads();
    return sh[0];
}

// ---------------- embedding gather ----------------
__global__ void embed_k(const int* __restrict__ tokens, const float* __restrict__ emb,
                        float* __restrict__ x) {
    int row = blockIdx.x;
    int tok = tokens[row];
    ((float4*)(x + (size_t)row * D_DIM))[threadIdx.x] =
        ((const float4*)(emb + (size_t)tok * D_DIM))[threadIdx.x];
}

// ---------------- GEMM core 128x128 (2-stage) ----------------
// 8 warps (2x4), warp tile 64x32 = 4x4 m16n8k8 mmas.
// SPLIT: 3xTF32 split hi/lo (~fp32 accuracy). SILU: apply silu to output.
template <bool SPLIT, bool SILU>
__device__ __forceinline__ void gemm_body(
    const float* __restrict__ A, const float* __restrict__ B, float* __restrict__ C,
    int N, int K, int bm, int bn, float* sm) {

    int tid  = threadIdx.x;
    int warp = tid >> 5, lane = tid & 31;
    int wm = warp >> 2, wn = warp & 3;
    int g = lane >> 2, tg = lane & 3;

    float acc[4][4][4];
    #pragma unroll
    for (int mt = 0; mt < 4; mt++)
        #pragma unroll
        for (int nt = 0; nt < 4; nt++)
            #pragma unroll
            for (int r = 0; r < 4; r++) acc[mt][nt][r] = 0.f;

    const float* Ab = A + (size_t)(bm * 128) * K;
    const float* Bb = B + bn * 128;

    int arow = tid >> 3;            // 0..31
    int acol = (tid & 7) * 4;
    int brow = tid >> 5;            // 0..7
    int bcol = (tid & 31) * 4;

    const int NT = K >> 5;

    {   // prologue: prefetch tile 0
        float* A0 = sm;
        float* B0 = sm + 2 * A_TILE;
        #pragma unroll
        for (int p = 0; p < 4; p++) {
            int r = arow + p * 32;
            cp16(&A0[r * A_STRIDE + acol], Ab + (size_t)r * K + acol);
        }
        #pragma unroll
        for (int p = 0; p < 4; p++) {
            int r = brow + p * 8;
            cp16(&B0[r * B_STRIDE + bcol], Bb + (size_t)r * N + bcol);
        }
        cp_commit();
    }

    for (int t = 0; t < NT; t++) {
        float* Ac = sm + (t & 1) * A_TILE;
        float* Bc = sm + 2 * A_TILE + (t & 1) * B_TILE;
        if (t + 1 < NT) {
            float* An = sm + ((t + 1) & 1) * A_TILE;
            float* Bn = sm + 2 * A_TILE + ((t + 1) & 1) * B_TILE;
            int k0 = (t + 1) * 32;
            #pragma unroll
            for (int p = 0; p < 4; p++) {
                int r = arow + p * 32;
                cp16(&An[r * A_STRIDE + acol], Ab + (size_t)r * K + k0 + acol);
            }
            #pragma unroll
            for (int p = 0; p < 4; p++) {
                int r = brow + p * 8;
                cp16(&Bn[r * B_STRIDE + bcol], Bb + (size_t)(k0 + r) * N + bcol);
            }
            cp_commit();
            asm volatile("cp.async.wait_group 1;");
        } else {
            asm volatile("cp.async.wait_group 0;");
        }
        __syncthreads();

        #pragma unroll
        for (int kk = 0; kk < 4; kk++) {
            if (!SPLIT) {
                uint32_t bf[4][2];
                #pragma unroll
                for (int nt = 0; nt < 4; nt++) {
                    int cbase = (kk * 8 + tg) * B_STRIDE + wn * 32 + nt * 8 + g;
                    bf[nt][0] = f2tf32(Bc[cbase]);
                    bf[nt][1] = f2tf32(Bc[cbase + 4 * B_STRIDE]);
                }
                #pragma unroll
                for (int mt = 0; mt < 4; mt++) {
                    int rbase = (wm * 64 + mt * 16) * A_STRIDE + kk * 8 + tg;
                    uint32_t af[4];
                    af[0] = f2tf32(Ac[rbase + g * A_STRIDE]);
                    af[1] = f2tf32(Ac[rbase + (g + 8) * A_STRIDE]);
                    af[2] = f2tf32(Ac[rbase + g * A_STRIDE + 4]);
                    af[3] = f2tf32(Ac[rbase + (g + 8) * A_STRIDE + 4]);
                    #pragma unroll
                    for (int nt = 0; nt < 4; nt++)
                        mma_tf32(acc[mt][nt], af, bf[nt]);
                }
            } else {
                uint32_t bfh[4][2], bfl[4][2];
                #pragma unroll
                for (int nt = 0; nt < 4; nt++) {
                    int cbase = (kk * 8 + tg) * B_STRIDE + wn * 32 + nt * 8 + g;
                    float f0 = Bc[cbase];
                    float f1 = Bc[cbase + 4 * B_STRIDE];
                    uint32_t h0 = f2tf32(f0), h1 = f2tf32(f1);
                    bfh[nt][0] = h0; bfh[nt][1] = h1;
                    bfl[nt][0] = f2tf32(f0 - __uint_as_float(h0));
                    bfl[nt][1] = f2tf32(f1 - __uint_as_float(h1));
                }
                #pragma unroll
                for (int mt = 0; mt < 4; mt++) {
                    int rbase = (wm * 64 + mt * 16) * A_STRIDE + kk * 8 + tg;
                    float f0 = Ac[rbase + g * A_STRIDE];
                    float f1 = Ac[rbase + (g + 8) * A_STRIDE];
                    float f2 = Ac[rbase + g * A_STRIDE + 4];
                    float f3 = Ac[rbase + (g + 8) * A_STRIDE + 4];
                    uint32_t afh[4], afl[4];
                    afh[0] = f2tf32(f0); afl[0] = f2tf32(f0 - __uint_as_float(afh[0]));
                    afh[1] = f2tf32(f1); afl[1] = f2tf32(f1 - __uint_as_float(afh[1]));
                    afh[2] = f2tf32(f2); afl[2] = f2tf32(f2 - __uint_as_float(afh[2]));
                    afh[3] = f2tf32(f3); afl[3] = f2tf32(f3 - __uint_as_float(afh[3]));
                    #pragma unroll
                    for (int nt = 0; nt < 4; nt++) {
                        mma_tf32(acc[mt][nt], afh, bfl[nt]);
                        mma_tf32(acc[mt][nt], afl, bfh[nt]);
                        mma_tf32(acc[mt][nt], afh, bfh[nt]);
                    }
                }
            }
        }
        __syncthreads();
    }

    int row0 = bm * 128 + wm * 64;
    int col0 = bn * 128 + wn * 32;
    #pragma unroll
    for (int mt = 0; mt < 4; mt++)
        #pragma unroll
        for (int nt = 0; nt < 4; nt++) {
            int row = row0 + mt * 16 + g;
            int col = col0 + nt * 8 + tg * 2;
            float v0 = acc[mt][nt][0], v1 = acc[mt][nt][1];
            float v2 = acc[mt][nt][2], v3 = acc[mt][nt][3];
            if (SILU) { v0 = silu1(v0); v1 = silu1(v1); v2 = silu1(v2); v3 = silu1(v3); }
            *(float2*)(C + (size_t)row * N + col) = make_float2(v0, v1);
            *(float2*)(C + (size_t)(row + 8) * N + col) = make_float2(v2, v3);
        }
}

// standalone GEMM
template <bool SPLIT>
__global__ __launch_bounds__(256, 2) void gemm_tf32(
    const float* __restrict__ A, const float* __restrict__ B, float* __restrict__ C,
    int M, int N, int K) {
    extern __shared__ float sm[];
    gemm_body<SPLIT, false>(A, B, C, N, K, blockIdx.y, blockIdx.x, sm);
}

// fused QKV: grid z selects weight/output; z==2 (V) applies silu in epilogue
__global__ __launch_bounds__(256, 2) void gemm_qkv(
    const float* __restrict__ X,
    const float* __restrict__ Wq, const float* __restrict__ Wk, const float* __restrict__ Wv,
    float* __restrict__ Q, float* __restrict__ Ko, float* __restrict__ Vo) {
    extern __shared__ float sm[];
    int z = blockIdx.z;
    const float* B = (z == 0) ? Wq : (z == 1) ? Wk : Wv;
    float* C = (z == 0) ? Q : (z == 1) ? Ko : Vo;
    if (z == 2)
        gemm_body<true, true>(X, B, C, D_DIM, D_DIM, blockIdx.y, blockIdx.x, sm);
    else
        gemm_body<true, false>(X, B, C, D_DIM, D_DIM, blockIdx.y, blockIdx.x, sm);
}

// ---------------- fused prep: beta, silu+l2norm(q), silu+l2norm(k), qk dot ----------------
// One block (256 threads) per row.
__global__ void prep_k(const float* __restrict__ x, const float* __restrict__ wb,
                       float* __restrict__ q, float* __restrict__ k,
                       float* __restrict__ beta, float* __restrict__ qk) {
    __shared__ float sh0[8], sh1[8], sh2[8], sh3[8];
    int row = blockIdx.x, tid = threadIdx.x;

    // beta = sigmoid(x . wb)
    const float4* xr = (const float4*)(x + (size_t)row * D_DIM);
    const float4* wr = (const float4*)wb;
    float4 xv = xr[tid], wv = wr[tid];
    float bd = xv.x * wv.x + xv.y * wv.y + xv.z * wv.z + xv.w * wv.w;
    float bsum = blockReduceSum(bd, sh0);
    if (tid == 0) beta[row] = 1.f / (1.f + expf(-bsum));

    // q := l2norm(silu(q))
    float4* qr = (float4*)(q + (size_t)row * D_DIM);
    float4 a = qr[tid];
    a.x = silu1(a.x); a.y = silu1(a.y); a.z = silu1(a.z); a.w = silu1(a.w);
    float qs = a.x * a.x + a.y * a.y + a.z * a.z + a.w * a.w;
    float qtot = blockReduceSum(qs, sh1);
    float qrs = rsqrtf(qtot + 1e-6f);
    a.x *= qrs; a.y *= qrs; a.z *= qrs; a.w *= qrs;
    qr[tid] = a;

    // k := l2norm(silu(k))
    float4* kr = (float4*)(k + (size_t)row * D_DIM);
    float4 b = kr[tid];
    b.x = silu1(b.x); b.y = silu1(b.y); b.z = silu1(b.z); b.w = silu1(b.w);
    float ks = b.x * b.x + b.y * b.y + b.z * b.z + b.w * b.w;
    float ktot = blockReduceSum(ks, sh2);
    float krs = rsqrtf(ktot + 1e-6f);
    b.x *= krs; b.y *= krs; b.z *= krs; b.w *= krs;
    kr[tid] = b;

    // qk = q_norm . k_norm
    float d = a.x * b.x + a.y * b.y + a.z * b.z + a.w * b.w;
    float dtot = blockReduceSum(d, sh3);
    if (tid == 0) qk[row] = dtot;
}

// ---------------- rmsnorm in place, one block per row ----------------
__global__ void rmsnorm_k(float* __restrict__ x, const float* __restrict__ w) {
    __shared__ float sh[8];
    float4* xr = (float4*)(x + (size_t)blockIdx.x * D_DIM);
    float4 a = xr[threadIdx.x];
    float ss = a.x * a.x + a.y * a.y + a.z * a.z + a.w * a.w;
    float tot = blockReduceSum(ss, sh);
    float r = rsqrtf(tot * (1.f / D_DIM) + 1e-5f);
    float4 wv = ((const float4*)w)[threadIdx.x];
    a.x *= r * wv.x; a.y *= r * wv.y; a.z *= r * wv.z; a.w *= r * wv.w;
    xr[threadIdx.x] = a;
}

// ---------------- layernorm in place, one block per row ----------------
__global__ void layernorm_k(float* __restrict__ x, const float* __restrict__ gg,
                            const float* __restrict__ bb) {
    __shared__ float sh1[8];
    __shared__ float sh2[8];
    float4* xr = (float4*)(x + (size_t)blockIdx.x * D_DIM);
    float4 a = xr[threadIdx.x];
    float s  = a.x + a.y + a.z + a.w;
    float ss = a.x * a.x + a.y * a.y + a.z * a.z + a.w * a.w;
    float S  = blockReduceSum(s, sh1);
    float SS = blockReduceSum(ss, sh2);
    float mu  = S * (1.f / D_DIM);
    float var = SS * (1.f / D_DIM) - mu * mu;
    float r = rsqrtf(var + 1e-5f);
    float4 gv = ((const float4*)gg)[threadIdx.x];
    float4 bv = ((const float4*)bb)[threadIdx.x];
    a.x = (a.x - mu) * r * gv.x + bv.x;
    a.y = (a.y - mu) * r * gv.y + bv.y;
    a.z = (a.z - mu) * r * gv.z + bv.z;
    a.w = (a.w - mu) * r * gv.w + bv.w;
    xr[threadIdx.x] = a;
}

// ---------------- delta-rule scan (R4 version, known good) ----------------
__global__ __launch_bounds__(256) void delta_scan(
    const float* __restrict__ q, const float* __restrict__ k,
    const float* __restrict__ v, const float* __restrict__ beta,
    const float* __restrict__ qk, float* __restrict__ o) {
    __shared__ float sk[1024];
    __shared__ float sq[1024];
    __shared__ float part[16 * 132];
    __shared__ float tot[16];

    int tid = threadIdx.x;
    int b = blockIdx.x >> 7;
    int ebase = (blockIdx.x & 127) * 8;
    int cg = tid >> 7;
    int rg = tid & 127;
    int d0 = rg * 8;
    int e0 = ebase + cg * 4;

    float2 S[4][4];
    #pragma unroll
    for (int r = 0; r < 4; r++)
        #pragma unroll
        for (int c = 0; c < 4; c++) S[r][c] = make_float2(0.f, 0.f);

    const float* qb = q + (size_t)b * S_DIM * D_DIM;
    const float* kb = k + (size_t)b * S_DIM * D_DIM;
    const float* vb = v + (size_t)b * S_DIM * D_DIM;
    const float* betab = beta + b * S_DIM;
    const float* qkb   = qk + b * S_DIM;
    float* ob = o + (size_t)b * S_DIM * D_DIM;

    int gj = tid >> 4, sl = tid & 15;   // reduce-stage mapping

    for (int t = 0; t < S_DIM; t++) {
        ((float4*)sk)[tid] = ((const float4*)(kb + (size_t)t * D_DIM))[tid];
        ((float4*)sq)[tid] = ((const float4*)(qb + (size_t)t * D_DIM))[tid];
        __syncthreads();

        float4 kA = *(float4*)(sk + d0);
        float4 kB = *(float4*)(sk + d0 + 4);
        float4 qA = *(float4*)(sq + d0);
        float4 qB = *(float4*)(sq + d0 + 4);
        float2 kv[4] = {{kA.x, kA.y}, {kA.z, kA.w}, {kB.x, kB.y}, {kB.z, kB.w}};
        float2 qv[4] = {{qA.x, qA.y}, {qA.z, qA.w}, {qB.x, qB.y}, {qB.z, qB.w}};

        float2 ks2[4], qs2[4];
        #pragma unroll
        for (int c = 0; c < 4; c++) { ks2[c] = make_float2(0.f, 0.f); qs2[c] = make_float2(0.f, 0.f); }
        #pragma unroll
        for (int c = 0; c < 4; c++)
            #pragma unroll
            for (int r = 0; r < 4; r++) {
                ks2[c] = ffma2(kv[r], S[r][c], ks2[c]);
                qs2[c] = ffma2(qv[r], S[r][c], qs2[c]);
            }
        #pragma unroll
        for (int c = 0; c < 4; c++) {
            part[(cg * 8 + c) * 132 + rg]     = ks2[c].x + ks2[c].y;
            part[(cg * 8 + 4 + c) * 132 + rg] = qs2[c].x + qs2[c].y;
        }
        __syncthreads();

        {   // 16 groups x 128 partials -> tot[16]
            const float* pg = part + gj * 132;
            float ps = 0.f;
            #pragma unroll
            for (int i = 0; i < 8; i++) ps += pg[sl + 16 * i];
            #pragma unroll
            for (int off = 8; off; off >>= 1) ps += __shfl_down_sync(0xffffffffu, ps, off, 16);
            if (sl == 0) tot[gj] = ps;
        }
        __syncthreads();

        float be  = betab[t];
        float qkt = qkb[t];
        float cc[4];
        #pragma unroll
        for (int c = 0; c < 4; c++) {
            float ksv = tot[cg * 8 + c];
            float vv  = __ldg(vb + (size_t)t * D_DIM + e0 + c);
            cc[c] = be * (vv - ksv);
            if (rg == 0) ob[(size_t)t * D_DIM + e0 + c] = tot[cg * 8 + 4 + c] + qkt * cc[c];
        }
        #pragma unroll
        for (int c = 0; c < 4; c++) {
            float2 c2 = make_float2(cc[c], cc[c]);
            #pragma unroll
            for (int r = 0; r < 4; r++) S[r][c] = ffma2(kv[r], c2, S[r][c]);
        }
        __syncthreads();
    }
}

// ---------------- host orchestration ----------------
extern "C" void kernel_launch(void* const* d_in, const int* in_sizes, int n_in,
                              void* d_out, int out_size) {
    const int*   tokens = (const int*)d_in[0];
    const float* emb    = (const float*)d_in[1];
    const float* Wq     = (const float*)d_in[2];
    const float* Wk     = (const float*)d_in[3];
    const float* Wv     = (const float*)d_in[4];
    const float* Wb     = (const float*)d_in[5];
    const float* Wo     = (const float*)d_in[6];
    const float* rms_w  = (const float*)d_in[7];
    const float* ln_g   = (const float*)d_in[8];
    const float* ln_b   = (const float*)d_in[9];
    const float* head_w = (const float*)d_in[10];
    float* out = (float*)d_out;

    float *x, *qb, *kb, *vb, *ob, *betab, *qkb;
    cudaGetSymbolAddress((void**)&x, g_x);
    cudaGetSymbolAddress((void**)&qb, g_q);
    cudaGetSymbolAddress((void**)&kb, g_k);
    cudaGetSymbolAddress((void**)&vb, g_v);
    cudaGetSymbolAddress((void**)&ob, g_o);
    cudaGetSymbolAddress((void**)&betab, g_beta);
    cudaGetSymbolAddress((void**)&qkb, g_qk);

    cudaFuncSetAttribute(gemm_tf32<true>,  cudaFuncAttributeMaxDynamicSharedMemorySize, GEMM_SMEM_BYTES);
    cudaFuncSetAttribute(gemm_tf32<false>, cudaFuncAttributeMaxDynamicSharedMemorySize, GEMM_SMEM_BYTES);
    cudaFuncSetAttribute(gemm_qkv,         cudaFuncAttributeMaxDynamicSharedMemorySize, GEMM_SMEM_BYTES);

    embed_k<<<NROWS, 256>>>(tokens, emb, x);   // launch 0

    dim3 g1(D_DIM / 128, NROWS / 128);          // (8,16)
    dim3 gqkv(D_DIM / 128, NROWS / 128, 3);     // (8,16,3)
    for (int l = 0; l < L_DIM; l++) {
        const float* wq = Wq + (size_t)l * D_DIM * D_DIM;
        const float* wk = Wk + (size_t)l * D_DIM * D_DIM;
        const float* wv = Wv + (size_t)l * D_DIM * D_DIM;
        const float* wb = Wb + (size_t)l * D_DIM;
        const float* wo = Wo + (size_t)l * D_DIM * D_DIM;
        const float* rw = rms_w + (size_t)l * D_DIM;

        gemm_qkv<<<gqkv, 256, GEMM_SMEM_BYTES>>>(x, wq, wk, wv, qb, kb, vb);  // 1
        prep_k<<<NROWS, 256>>>(x, wb, qb, kb, betab, qkb);                    // 2
        delta_scan<<<256, 256>>>(qb, kb, vb, betab, qkb, ob);                 // 3  <- profiled
        rmsnorm_k<<<NROWS, 256>>>(ob, rw);
        gemm_tf32<true><<<g1, 256, GEMM_SMEM_BYTES>>>(ob, wo, x, NROWS, D_DIM, D_DIM);
    }
    layernorm_k<<<NROWS, 256>>>(x, ln_g, ln_b);

    dim3 g2(V_DIM / 128, NROWS / 128);   // (250,16)
    gemm_tf32<false><<<g2, 256, GEMM_SMEM_BYTES>>>(x, head_w, out, NROWS, V_DIM, D_DIM);
}